// round 1
// baseline (speedup 1.0000x reference)
#include <cuda_runtime.h>

// Scratch (device globals — no allocation allowed in kernel_launch)
#define NMAX 100000
__device__ float g_inv[NMAX];   // 1/||x_n||          (raw features)
__device__ float g_c[NMAX];     // sum of edge cosines scattered to dst
__device__ float g_deg[NMAX];   // in-degree (float, exact for counts < 2^24)
__device__ float g_rn[NMAX];    // 1/max(||x_new_n||, eps)

// ---------------------------------------------------------------------------
// Kernel 1: per-node inverse norm of raw x + zero the accumulators.
// One warp per node; lane l loads float4 at offset l (32*4 = 128 floats).
// ---------------------------------------------------------------------------
__global__ void node_norm_kernel(const float* __restrict__ x, int n)
{
    int warp = (blockIdx.x * blockDim.x + threadIdx.x) >> 5;
    int lane = threadIdx.x & 31;
    if (warp >= n) return;

    const float4* xp = reinterpret_cast<const float4*>(x + (size_t)warp * 128);
    float4 v = xp[lane];
    float s = v.x * v.x + v.y * v.y + v.z * v.z + v.w * v.w;
    #pragma unroll
    for (int o = 16; o; o >>= 1) s += __shfl_xor_sync(0xFFFFFFFFu, s, o);

    if (lane == 0) {
        g_inv[warp] = rsqrtf(s);
        g_c[warp]   = 0.0f;
        g_deg[warp] = 0.0f;
    }
}

// ---------------------------------------------------------------------------
// Kernel 2: per-edge cosine of normalized raw features, scatter-add to dst.
// One warp per edge.
// ---------------------------------------------------------------------------
__global__ void edge_sim_kernel(const float* __restrict__ x,
                                const int* __restrict__ ei,  // [2, E] flattened
                                int ecount)
{
    int warp = (blockIdx.x * blockDim.x + threadIdx.x) >> 5;
    int lane = threadIdx.x & 31;
    if (warp >= ecount) return;

    int r = ei[warp];
    int c = ei[ecount + warp];

    const float4* a = reinterpret_cast<const float4*>(x + (size_t)r * 128);
    const float4* b = reinterpret_cast<const float4*>(x + (size_t)c * 128);
    float4 va = a[lane];
    float4 vb = b[lane];
    float s = va.x * vb.x + va.y * vb.y + va.z * vb.z + va.w * vb.w;
    #pragma unroll
    for (int o = 16; o; o >>= 1) s += __shfl_xor_sync(0xFFFFFFFFu, s, o);

    if (lane == 0) {
        float e = s * g_inv[r] * g_inv[c];
        atomicAdd(&g_c[c], e);
        atomicAdd(&g_deg[c], 1.0f);
    }
}

// ---------------------------------------------------------------------------
// Kernel 3: per-node masks -> final prompt vector -> x_new -> new inv norm.
// One warp per node. Writes x_new into out[0 : n*128].
// ---------------------------------------------------------------------------
__global__ void prompt_kernel(const float* __restrict__ x,
                              const float* __restrict__ p_sim,
                              const float* __restrict__ p_deg,
                              const float* __restrict__ p_oth,
                              float* __restrict__ out,
                              int n)
{
    int warp = (blockIdx.x * blockDim.x + threadIdx.x) >> 5;
    int lane = threadIdx.x & 31;
    if (warp >= n) return;

    float deg = g_deg[warp];
    float csum = g_c[warp];
    // csim = deg>0 ? csum/deg : +inf  (inf <= 0.2 is false)
    bool msim = (deg > 0.0f) && (csum / deg <= 0.2f);
    bool mdeg = (deg <= 3.0f);
    bool moth = !(msim || mdeg);
    // plen in {1,2}: 'other' fires exactly when neither of the first two does.
    float plen = (float)((int)msim + (int)mdeg + (int)moth);
    float invp = 1.0f / plen;

    float4 va = reinterpret_cast<const float4*>(x + (size_t)warp * 128)[lane];
    float4 fs = {0.f, 0.f, 0.f, 0.f};
    if (msim) {
        float4 p = reinterpret_cast<const float4*>(p_sim)[lane];
        fs.x += p.x; fs.y += p.y; fs.z += p.z; fs.w += p.w;
    }
    if (mdeg) {
        float4 p = reinterpret_cast<const float4*>(p_deg)[lane];
        fs.x += p.x; fs.y += p.y; fs.z += p.z; fs.w += p.w;
    }
    if (moth) {
        float4 p = reinterpret_cast<const float4*>(p_oth)[lane];
        fs.x += p.x; fs.y += p.y; fs.z += p.z; fs.w += p.w;
    }
    float4 xn;
    xn.x = va.x + fs.x * invp;
    xn.y = va.y + fs.y * invp;
    xn.z = va.z + fs.z * invp;
    xn.w = va.w + fs.w * invp;

    reinterpret_cast<float4*>(out + (size_t)warp * 128)[lane] = xn;

    float s = xn.x * xn.x + xn.y * xn.y + xn.z * xn.z + xn.w * xn.w;
    #pragma unroll
    for (int o = 16; o; o >>= 1) s += __shfl_xor_sync(0xFFFFFFFFu, s, o);
    if (lane == 0) {
        g_rn[warp] = 1.0f / fmaxf(sqrtf(s), 1e-8f);
    }
}

// ---------------------------------------------------------------------------
// Kernel 4: per-edge prune cosine on prompted features.
// keep[e] = (dot(x_new[r], x_new[c]) * rn[r] * rn[c] >= 0.1) ? 1 : 0
// ---------------------------------------------------------------------------
__global__ void prune_kernel(const float* __restrict__ xn,
                             const int* __restrict__ ei,
                             float* __restrict__ keep,
                             int ecount)
{
    int warp = (blockIdx.x * blockDim.x + threadIdx.x) >> 5;
    int lane = threadIdx.x & 31;
    if (warp >= ecount) return;

    int r = ei[warp];
    int c = ei[ecount + warp];

    const float4* a = reinterpret_cast<const float4*>(xn + (size_t)r * 128);
    const float4* b = reinterpret_cast<const float4*>(xn + (size_t)c * 128);
    float4 va = a[lane];
    float4 vb = b[lane];
    float s = va.x * vb.x + va.y * vb.y + va.z * vb.z + va.w * vb.w;
    #pragma unroll
    for (int o = 16; o; o >>= 1) s += __shfl_xor_sync(0xFFFFFFFFu, s, o);

    if (lane == 0) {
        float cosv = s * g_rn[r] * g_rn[c];
        keep[warp] = (cosv >= 0.1f) ? 1.0f : 0.0f;
    }
}

// ---------------------------------------------------------------------------
extern "C" void kernel_launch(void* const* d_in, const int* in_sizes, int n_in,
                              void* d_out, int out_size)
{
    const float* x     = (const float*)d_in[0];
    const int*   ei    = (const int*)d_in[1];
    const float* p_sim = (const float*)d_in[2];
    const float* p_deg = (const float*)d_in[3];
    const float* p_oth = (const float*)d_in[4];
    float* out = (float*)d_out;

    int n = in_sizes[0] / 128;       // nodes
    int e = in_sizes[1] / 2;         // edges

    const int TPB = 256;             // 8 warps per block
    int node_blocks = (n * 32 + TPB - 1) / TPB;
    int edge_blocks = (e * 32 + TPB - 1) / TPB;

    node_norm_kernel<<<node_blocks, TPB>>>(x, n);
    edge_sim_kernel<<<edge_blocks, TPB>>>(x, ei, e);
    prompt_kernel<<<node_blocks, TPB>>>(x, p_sim, p_deg, p_oth, out, n);
    prune_kernel<<<edge_blocks, TPB>>>(out, ei, out + (size_t)n * 128, e);
}

// round 2
// speedup vs baseline: 2.2251x; 2.2251x over previous
#include <cuda_runtime.h>

#define NMAX 100000
#define EMAX 640000

// Scratch (device globals — allocation is forbidden)
__device__ float  g_inv[NMAX];     // 1/||x_n|| (raw)
__device__ float  g_c[NMAX];       // scatter-sum of edge cosines at dst
__device__ float  g_deg[NMAX];     // in-degree
__device__ float4 g_dots[NMAX];    // {dot(x,p_sim), dot(x,p_deg), dot(x,p_oth), -}
__device__ float  g_node[NMAX*8];  // per node: {D_F0, D_F1, D_F2, D_F3, rn, fidx, 0, 0}
__device__ float  g_dote[EMAX];    // dot(x_r, x_c) per edge
__device__ float  g_FF[16];        // dot(F_j, F_k)

__device__ __forceinline__ float dot4(float4 a, float4 b) {
    return a.x*b.x + a.y*b.y + a.z*b.z + a.w*b.w;
}

// ---------------------------------------------------------------------------
// FF table: F_0=p_sim, F_1=p_deg, F_2=(p_sim+p_deg)/2, F_3=p_oth
// 16 warps, one (j,k) pair each.
// ---------------------------------------------------------------------------
__global__ void ff_kernel(const float* __restrict__ p0,
                          const float* __restrict__ p1,
                          const float* __restrict__ p2)
{
    int w = threadIdx.x >> 5;          // 0..15
    int lane = threadIdx.x & 31;
    int j = w >> 2, k = w & 3;

    float4 a0 = reinterpret_cast<const float4*>(p0)[lane];
    float4 a1 = reinterpret_cast<const float4*>(p1)[lane];
    float4 a2 = reinterpret_cast<const float4*>(p2)[lane];

    auto combo = [&](int t) -> float4 {
        if (t == 0) return a0;
        if (t == 1) return a1;
        if (t == 2) return make_float4((a0.x+a1.x)*0.5f, (a0.y+a1.y)*0.5f,
                                       (a0.z+a1.z)*0.5f, (a0.w+a1.w)*0.5f);
        return a2;
    };
    float s = dot4(combo(j), combo(k));
    #pragma unroll
    for (int o = 16; o; o >>= 1) s += __shfl_xor_sync(0xFFFFFFFFu, s, o);
    if (lane == 0) g_FF[w] = s;
}

// ---------------------------------------------------------------------------
// Kernel A: per-node |x| + dots with the 3 prompts + zero accumulators.
// One warp per node, 1 float4 per lane. 4 independent reduction chains.
// ---------------------------------------------------------------------------
__global__ void nodeA_kernel(const float* __restrict__ x,
                             const float* __restrict__ p0,
                             const float* __restrict__ p1,
                             const float* __restrict__ p2,
                             int n)
{
    int warp = (blockIdx.x * blockDim.x + threadIdx.x) >> 5;
    int lane = threadIdx.x & 31;
    if (warp >= n) return;

    float4 v = reinterpret_cast<const float4*>(x + (size_t)warp * 128)[lane];
    float4 a = reinterpret_cast<const float4*>(p0)[lane];
    float4 b = reinterpret_cast<const float4*>(p1)[lane];
    float4 c = reinterpret_cast<const float4*>(p2)[lane];

    float s0 = dot4(v, v);
    float s1 = dot4(v, a);
    float s2 = dot4(v, b);
    float s3 = dot4(v, c);
    #pragma unroll
    for (int o = 16; o; o >>= 1) {
        s0 += __shfl_xor_sync(0xFFFFFFFFu, s0, o);
        s1 += __shfl_xor_sync(0xFFFFFFFFu, s1, o);
        s2 += __shfl_xor_sync(0xFFFFFFFFu, s2, o);
        s3 += __shfl_xor_sync(0xFFFFFFFFu, s3, o);
    }
    if (lane == 0) {
        g_inv[warp]  = rsqrtf(s0);
        g_dots[warp] = make_float4(s1, s2, s3, 0.0f);
        g_c[warp]    = 0.0f;
        g_deg[warp]  = 0.0f;
    }
}

// ---------------------------------------------------------------------------
// Kernel B: per-edge raw dot -> store; cosine -> scatter-add at dst.
// 8 lanes per edge, 4 edges per warp. 8 independent LDG.128 per lane.
// ---------------------------------------------------------------------------
__global__ void edgeB_kernel(const float* __restrict__ x,
                             const int* __restrict__ ei,
                             int E)
{
    int gid  = blockIdx.x * blockDim.x + threadIdx.x;
    int warp = gid >> 5;
    int lane = threadIdx.x & 31;
    int sub  = lane >> 3;   // edge within warp (0..3)
    int sl   = lane & 7;    // lane within edge group

    int e = warp * 4 + sub;
    bool valid = (e < E);
    int ec = valid ? e : 0;   // keep all lanes active for shuffles

    int r = ei[ec];
    int c = ei[E + ec];

    const float4* A = reinterpret_cast<const float4*>(x + (size_t)r * 128);
    const float4* B = reinterpret_cast<const float4*>(x + (size_t)c * 128);

    float s = 0.0f;
    #pragma unroll
    for (int i = 0; i < 4; i++) {
        float4 va = A[sl + 8 * i];
        float4 vb = B[sl + 8 * i];
        s += dot4(va, vb);
    }
    s += __shfl_xor_sync(0xFFFFFFFFu, s, 4);
    s += __shfl_xor_sync(0xFFFFFFFFu, s, 2);
    s += __shfl_xor_sync(0xFFFFFFFFu, s, 1);

    if (sl == 0 && valid) {
        g_dote[e] = s;
        float ecos = s * g_inv[r] * g_inv[c];
        atomicAdd(&g_c[c], ecos);
        atomicAdd(&g_deg[c], 1.0f);
    }
}

// ---------------------------------------------------------------------------
// Kernel C: masks -> prompt combo -> x_new (to out) -> rn + per-node record.
// ---------------------------------------------------------------------------
__global__ void nodeC_kernel(const float* __restrict__ x,
                             const float* __restrict__ p0,
                             const float* __restrict__ p1,
                             const float* __restrict__ p2,
                             float* __restrict__ out,
                             int n)
{
    int warp = (blockIdx.x * blockDim.x + threadIdx.x) >> 5;
    int lane = threadIdx.x & 31;
    if (warp >= n) return;

    float deg  = g_deg[warp];   // broadcast load
    float csum = g_c[warp];
    bool msim = (deg > 0.0f) && (csum / deg <= 0.2f);
    bool mdeg = (deg <= 3.0f);
    int fidx = msim ? (mdeg ? 2 : 0) : (mdeg ? 1 : 3);

    float4 v = reinterpret_cast<const float4*>(x + (size_t)warp * 128)[lane];
    float4 f;
    if (fidx == 0)      f = reinterpret_cast<const float4*>(p0)[lane];
    else if (fidx == 1) f = reinterpret_cast<const float4*>(p1)[lane];
    else if (fidx == 2) {
        float4 a = reinterpret_cast<const float4*>(p0)[lane];
        float4 b = reinterpret_cast<const float4*>(p1)[lane];
        f = make_float4((a.x+b.x)*0.5f, (a.y+b.y)*0.5f, (a.z+b.z)*0.5f, (a.w+b.w)*0.5f);
    } else               f = reinterpret_cast<const float4*>(p2)[lane];

    float4 xn = make_float4(v.x + f.x, v.y + f.y, v.z + f.z, v.w + f.w);
    reinterpret_cast<float4*>(out + (size_t)warp * 128)[lane] = xn;

    float s = dot4(xn, xn);
    #pragma unroll
    for (int o = 16; o; o >>= 1) s += __shfl_xor_sync(0xFFFFFFFFu, s, o);

    if (lane == 0) {
        float rn = 1.0f / fmaxf(sqrtf(s), 1e-8f);
        float4 d = g_dots[warp];   // {d_sim, d_deg, d_oth}
        float4* nd = reinterpret_cast<float4*>(g_node + (size_t)warp * 8);
        nd[0] = make_float4(d.x, d.y, (d.x + d.y) * 0.5f, d.z);  // D_{F0..F3}
        nd[1] = make_float4(rn, (float)fidx, 0.0f, 0.0f);
    }
}

// ---------------------------------------------------------------------------
// Kernel D: edge pruning via decomposition. One thread per edge, ~70B/edge.
// cos = (dote + dot(x_r,F_c) + dot(x_c,F_r) + FF[fr][fc]) * rn_r * rn_c
// ---------------------------------------------------------------------------
__global__ void edgeD_kernel(const int* __restrict__ ei,
                             float* __restrict__ keep,
                             int E)
{
    int e = blockIdx.x * blockDim.x + threadIdx.x;
    if (e >= E) return;

    int r = ei[e];
    int c = ei[E + e];

    const float4* nr = reinterpret_cast<const float4*>(g_node + (size_t)r * 8);
    const float4* nc = reinterpret_cast<const float4*>(g_node + (size_t)c * 8);
    float4 r0 = nr[0], r1 = nr[1];
    float4 c0 = nc[0], c1 = nc[1];

    int fr = (int)r1.y;
    int fc = (int)c1.y;

    float drFc = (fc == 0) ? r0.x : (fc == 1) ? r0.y : (fc == 2) ? r0.z : r0.w;
    float dcFr = (fr == 0) ? c0.x : (fr == 1) ? c0.y : (fr == 2) ? c0.z : c0.w;

    float dot_new = g_dote[e] + drFc + dcFr + g_FF[fr * 4 + fc];
    float cosv = dot_new * r1.x * c1.x;
    keep[e] = (cosv >= 0.1f) ? 1.0f : 0.0f;
}

// ---------------------------------------------------------------------------
extern "C" void kernel_launch(void* const* d_in, const int* in_sizes, int n_in,
                              void* d_out, int out_size)
{
    const float* x     = (const float*)d_in[0];
    const int*   ei    = (const int*)d_in[1];
    const float* p_sim = (const float*)d_in[2];
    const float* p_deg = (const float*)d_in[3];
    const float* p_oth = (const float*)d_in[4];
    float* out = (float*)d_out;

    int n = in_sizes[0] / 128;
    int e = in_sizes[1] / 2;

    const int TPB = 256;
    int node_blocks  = (n * 32 + TPB - 1) / TPB;
    int edgeB_blocks = (e * 8  + TPB - 1) / TPB;  // 4 edges per warp
    int edgeD_blocks = (e + TPB - 1) / TPB;

    ff_kernel<<<1, 512>>>(p_sim, p_deg, p_oth);
    nodeA_kernel<<<node_blocks, TPB>>>(x, p_sim, p_deg, p_oth, n);
    edgeB_kernel<<<edgeB_blocks, TPB>>>(x, ei, e);
    nodeC_kernel<<<node_blocks, TPB>>>(x, p_sim, p_deg, p_oth, out, n);
    edgeD_kernel<<<edgeD_blocks, TPB>>>(ei, out + (size_t)n * 128, e);
}